// round 2
// baseline (speedup 1.0000x reference)
#include <cuda_runtime.h>
#include <cstdint>

#define N_NODES 100000
#define N_EDGES 800000
#define FEATS 128

// Scratch (allocation-free rule: device globals). 16B-aligned for float4/red.v4.
__device__ __align__(16) float g_accum[(size_t)N_NODES * FEATS];  // 51.2 MB
__device__ __align__(16) float g_deg[N_NODES];
__device__ __align__(16) float g_WsT[FEATS * FEATS];  // W_self transposed [k][o]
__device__ __align__(16) float g_WnT[FEATS * FEATS];  // W_neigh transposed [k][o]
__device__ int g_is64;

// ---------------------------------------------------------------------------
// Kernel 0: detect index width. int64 values < 2^31 => all odd 32-bit words 0.
// ---------------------------------------------------------------------------
__global__ void k_detect(const int* __restrict__ src_raw) {
    if (threadIdx.x == 0 && blockIdx.x == 0) {
        int is64 = 1;
        for (int i = 0; i < 256; ++i) {
            if (src_raw[2 * i + 1] != 0) { is64 = 0; break; }
        }
        g_is64 = is64;
    }
}

// ---------------------------------------------------------------------------
// Kernel 1: zero accumulators
// ---------------------------------------------------------------------------
__global__ void k_init() {
    int i = blockIdx.x * blockDim.x + threadIdx.x;
    float4 z = make_float4(0.f, 0.f, 0.f, 0.f);
    if (i < N_NODES * 32) ((float4*)g_accum)[i] = z;
    if (i < N_NODES / 4) ((float4*)g_deg)[i] = z;
}

// ---------------------------------------------------------------------------
// Kernel 2: transpose both weight matrices (W[o][k] -> WT[k][o])
// ---------------------------------------------------------------------------
__global__ void k_transpose(const float* __restrict__ Wn, const float* __restrict__ Ws) {
    int i = blockIdx.x * blockDim.x + threadIdx.x;
    if (i < FEATS * FEATS) {
        int o = i >> 7;
        int k = i & 127;
        g_WnT[k * FEATS + o] = Wn[i];
        g_WsT[k * FEATS + o] = Ws[i];
    }
}

// ---------------------------------------------------------------------------
// Kernel 3: edge scatter — one warp per edge, vectorized global reduction
// ---------------------------------------------------------------------------
__device__ __forceinline__ void red_add_v4(float* p, float4 v) {
    asm volatile("red.global.add.v4.f32 [%0], {%1, %2, %3, %4};"
                 :: "l"(p), "f"(v.x), "f"(v.y), "f"(v.z), "f"(v.w)
                 : "memory");
}

__global__ __launch_bounds__(256) void k_scatter(const float* __restrict__ feat,
                                                 const void* __restrict__ src_p,
                                                 const void* __restrict__ dst_p) {
    int e = (blockIdx.x * blockDim.x + threadIdx.x) >> 5;  // warp per edge
    int lane = threadIdx.x & 31;
    if (e >= N_EDGES) return;
    long long s, d;
    if (g_is64) {
        s = ((const long long*)src_p)[e];
        d = ((const long long*)dst_p)[e];
    } else {
        s = ((const int*)src_p)[e];
        d = ((const int*)dst_p)[e];
    }
    // Defensive: wrong dtype guess gives rel_err failure, not a crash.
    if (s < 0 || s >= N_NODES || d < 0 || d >= N_NODES) return;
    const float4* frow = (const float4*)(feat + (size_t)s * FEATS);
    float4 v = frow[lane];  // 32 lanes x 16B = full 512B row
    red_add_v4(g_accum + (size_t)d * FEATS + (size_t)lane * 4, v);
    if (lane == 0) atomicAdd(&g_deg[d], 1.0f);
}

// ---------------------------------------------------------------------------
// Kernel 4: fused dual-GEMM + mean + bias epilogue
//   out[m][o] = sum_k feat[m][k]*Ws[o][k] + inv_deg[m]*sum_k accum[m][k]*Wn[o][k] + b[o]
// BM=64, BN=128, BK=16; 256 threads; each thread 8x4 outputs.
// ---------------------------------------------------------------------------
__global__ __launch_bounds__(256) void k_gemm_fused(const float* __restrict__ feat,
                                                    const float* __restrict__ b_self,
                                                    float* __restrict__ out) {
    __shared__ float As[16][64];    // transposed A tile: As[k][m]
    __shared__ float Bs[16][128];   // B tile (k-major): Bs[k][o]
    __shared__ float sinv[64];

    int tid = threadIdx.x;
    int m0 = blockIdx.x * 64;
    int tx = tid & 31;   // 32 column groups of 4
    int ty = tid >> 5;   // 8 row groups of 8

    if (tid < 64) {
        int m = m0 + tid;
        float d = (m < N_NODES) ? g_deg[m] : 1.0f;
        sinv[tid] = 1.0f / fmaxf(d, 1.0f);
    }

    float acc[8][4];
#pragma unroll
    for (int i = 0; i < 8; i++)
#pragma unroll
        for (int j = 0; j < 4; j++) acc[i][j] = 0.f;

    int la_m = tid >> 2;          // 0..63
    int la_k = (tid & 3) * 4;     // 0,4,8,12
    int gm = m0 + la_m;
    bool m_ok = gm < N_NODES;

#pragma unroll
    for (int pass = 0; pass < 2; ++pass) {
        const float* A = pass ? g_accum : feat;
        const float* B = pass ? g_WnT : g_WsT;

        for (int kt = 0; kt < 8; ++kt) {
            int k0 = kt * 16;
            float4 va = make_float4(0.f, 0.f, 0.f, 0.f);
            if (m_ok) va = *(const float4*)(A + (size_t)gm * FEATS + k0 + la_k);
            if (pass) {
                float scale = sinv[la_m];
                va.x *= scale; va.y *= scale; va.z *= scale; va.w *= scale;
            }
            As[la_k + 0][la_m] = va.x;
            As[la_k + 1][la_m] = va.y;
            As[la_k + 2][la_m] = va.z;
            As[la_k + 3][la_m] = va.w;
#pragma unroll
            for (int h = 0; h < 2; ++h) {
                int idx = (tid + h * 256) * 4;   // 0..2047
                int k = idx >> 7;
                int o = idx & 127;
                *(float4*)&Bs[k][o] = *(const float4*)(B + (size_t)(k0 + k) * FEATS + o);
            }
            __syncthreads();
#pragma unroll
            for (int k = 0; k < 16; ++k) {
                float4 a0 = *(float4*)&As[k][ty * 8];       // warp broadcast
                float4 a1 = *(float4*)&As[k][ty * 8 + 4];
                float4 bv = *(float4*)&Bs[k][tx * 4];       // conflict-free
                float av[8] = {a0.x, a0.y, a0.z, a0.w, a1.x, a1.y, a1.z, a1.w};
                float bb[4] = {bv.x, bv.y, bv.z, bv.w};
#pragma unroll
                for (int i = 0; i < 8; i++)
#pragma unroll
                    for (int j = 0; j < 4; j++) acc[i][j] += av[i] * bb[j];
            }
            __syncthreads();
        }
    }

    float4 bias = *(const float4*)(b_self + tx * 4);
#pragma unroll
    for (int i = 0; i < 8; i++) {
        int m = m0 + ty * 8 + i;
        if (m < N_NODES) {
            float4 r;
            r.x = acc[i][0] + bias.x;
            r.y = acc[i][1] + bias.y;
            r.z = acc[i][2] + bias.z;
            r.w = acc[i][3] + bias.w;
            *(float4*)(out + (size_t)m * FEATS + tx * 4) = r;
        }
    }
}

// ---------------------------------------------------------------------------
extern "C" void kernel_launch(void* const* d_in, const int* in_sizes, int n_in,
                              void* d_out, int out_size) {
    const float* feat = (const float*)d_in[0];
    const void*  src  = d_in[1];
    const void*  dst  = d_in[2];
    const float* Wn   = (const float*)d_in[3];  // W_neigh [OUT][IN]
    const float* Ws   = (const float*)d_in[4];  // W_self  [OUT][IN]
    const float* b    = (const float*)d_in[5];
    float*       out  = (float*)d_out;

    k_detect<<<1, 32>>>((const int*)src);
    k_init<<<(N_NODES * 32 + 255) / 256, 256>>>();
    k_transpose<<<(FEATS * FEATS + 255) / 256, 256>>>(Wn, Ws);
    k_scatter<<<(N_EDGES + 7) / 8, 256>>>(feat, src, dst);
    k_gemm_fused<<<(N_NODES + 63) / 64, 256>>>(feat, b, out);
}

// round 3
// speedup vs baseline: 1.0026x; 1.0026x over previous
#include <cuda_runtime.h>
#include <cstdint>

#define N_NODES 100000
#define N_EDGES 800000
#define FEATS 128
#define NB1 196  // ceil(100000/512) scan phase-1 blocks

// Scratch (allocation-free rule: device globals)
__device__ __align__(16) float g_accum[(size_t)N_NODES * FEATS];  // mean-aggregated rows
__device__ __align__(16) float g_WsT[FEATS * FEATS];  // W_self^T  [k][o]
__device__ __align__(16) float g_WnT[FEATS * FEATS];  // W_neigh^T [k][o]
__device__ int g_cnt[N_NODES];
__device__ int g_row[N_NODES];     // exclusive offsets
__device__ int g_cursor[N_NODES];
__device__ int g_esrc[N_EDGES];    // src ids grouped by dst
__device__ int g_btot[NB1];
__device__ int g_boff[NB1];
__device__ int g_is64;

// ---------------------------------------------------------------------------
// f32x2 packed-math helpers (sm_100+: FFMA2)
// ---------------------------------------------------------------------------
__device__ __forceinline__ unsigned long long dup2(float a) {
    unsigned long long r;
    asm("mov.b64 %0, {%1, %1};" : "=l"(r) : "f"(a));
    return r;
}
__device__ __forceinline__ void ffma2(unsigned long long& c, unsigned long long a,
                                      unsigned long long b) {
    asm("fma.rn.f32x2 %0, %1, %2, %3;" : "=l"(c) : "l"(a), "l"(b), "l"(c));
}
__device__ __forceinline__ float2 unpack2(unsigned long long v) {
    float2 r;
    asm("mov.b64 {%0, %1}, %2;" : "=f"(r.x), "=f"(r.y) : "l"(v));
    return r;
}

// ---------------------------------------------------------------------------
// Kernel 0: detect index width (int64 vals < 2^31 => odd 32-bit words all 0)
// ---------------------------------------------------------------------------
__global__ void k_detect(const int* __restrict__ src_raw) {
    if (threadIdx.x == 0) {
        int is64 = 1;
        for (int i = 0; i < 256; ++i)
            if (src_raw[2 * i + 1] != 0) { is64 = 0; break; }
        g_is64 = is64;
    }
}

__device__ __forceinline__ int load_idx(const void* p, int e) {
    return g_is64 ? (int)((const long long*)p)[e] : ((const int*)p)[e];
}

// ---------------------------------------------------------------------------
// CSR build
// ---------------------------------------------------------------------------
__global__ void k_zero_cnt() {
    int i = blockIdx.x * blockDim.x + threadIdx.x;
    if (i < N_NODES) g_cnt[i] = 0;
}

__global__ __launch_bounds__(256) void k_count(const void* __restrict__ dst_p) {
    int e = blockIdx.x * blockDim.x + threadIdx.x;
    if (e >= N_EDGES) return;
    int d = load_idx(dst_p, e);
    if ((unsigned)d < N_NODES) atomicAdd(&g_cnt[d], 1);
}

__global__ __launch_bounds__(512) void k_scan1() {
    __shared__ int wsum[16];
    int i = blockIdx.x * 512 + threadIdx.x;
    int lane = threadIdx.x & 31, w = threadIdx.x >> 5;
    int v = (i < N_NODES) ? g_cnt[i] : 0;
    int incl = v;
#pragma unroll
    for (int o = 1; o < 32; o <<= 1) {
        int t = __shfl_up_sync(0xffffffffu, incl, o);
        if (lane >= o) incl += t;
    }
    if (lane == 31) wsum[w] = incl;
    __syncthreads();
    if (threadIdx.x < 16) {
        int x = wsum[threadIdx.x];
        int incl2 = x;
#pragma unroll
        for (int o = 1; o < 16; o <<= 1) {
            int t = __shfl_up_sync(0x0000ffffu, incl2, o);
            if ((int)threadIdx.x >= o) incl2 += t;
        }
        wsum[threadIdx.x] = incl2 - x;  // exclusive warp offset
        if (threadIdx.x == 15) g_btot[blockIdx.x] = incl2;
    }
    __syncthreads();
    if (i < N_NODES) g_row[i] = (incl - v) + wsum[w];
}

__global__ __launch_bounds__(256) void k_scan2() {
    __shared__ int wsum[8];
    int i = threadIdx.x;
    int lane = i & 31, w = i >> 5;
    int v = (i < NB1) ? g_btot[i] : 0;
    int incl = v;
#pragma unroll
    for (int o = 1; o < 32; o <<= 1) {
        int t = __shfl_up_sync(0xffffffffu, incl, o);
        if (lane >= o) incl += t;
    }
    if (lane == 31) wsum[w] = incl;
    __syncthreads();
    if (i < 8) {
        int x = wsum[i];
        int incl2 = x;
#pragma unroll
        for (int o = 1; o < 8; o <<= 1) {
            int t = __shfl_up_sync(0x000000ffu, incl2, o);
            if (i >= o) incl2 += t;
        }
        wsum[i] = incl2 - x;
    }
    __syncthreads();
    if (i < NB1) g_boff[i] = (incl - v) + wsum[w];
}

__global__ void k_scan3() {
    int i = blockIdx.x * blockDim.x + threadIdx.x;
    if (i < N_NODES) {
        int r = g_row[i] + g_boff[i >> 9];
        g_row[i] = r;
        g_cursor[i] = r;
    }
}

__global__ __launch_bounds__(256) void k_reorder(const void* __restrict__ src_p,
                                                 const void* __restrict__ dst_p) {
    int e = blockIdx.x * blockDim.x + threadIdx.x;
    if (e >= N_EDGES) return;
    int s = load_idx(src_p, e);
    int d = load_idx(dst_p, e);
    if ((unsigned)d >= N_NODES || (unsigned)s >= N_NODES) return;
    int pos = atomicAdd(&g_cursor[d], 1);
    g_esrc[pos] = s;
}

// ---------------------------------------------------------------------------
// Gather: one warp per dst node; accumulate feat rows in registers, write mean.
// ---------------------------------------------------------------------------
__global__ __launch_bounds__(256) void k_gather(const float* __restrict__ feat) {
    int node = (blockIdx.x * blockDim.x + threadIdx.x) >> 5;
    int lane = threadIdx.x & 31;
    if (node >= N_NODES) return;
    int start = g_row[node];
    int deg = g_cnt[node];
    const int* es = g_esrc + start;

    float4 acc = make_float4(0.f, 0.f, 0.f, 0.f);
    int j = 0;
    for (; j + 4 <= deg; j += 4) {
        int s0 = es[j], s1 = es[j + 1], s2 = es[j + 2], s3 = es[j + 3];
        float4 v0 = ((const float4*)(feat + (size_t)s0 * FEATS))[lane];
        float4 v1 = ((const float4*)(feat + (size_t)s1 * FEATS))[lane];
        float4 v2 = ((const float4*)(feat + (size_t)s2 * FEATS))[lane];
        float4 v3 = ((const float4*)(feat + (size_t)s3 * FEATS))[lane];
        acc.x += v0.x + v1.x + v2.x + v3.x;
        acc.y += v0.y + v1.y + v2.y + v3.y;
        acc.z += v0.z + v1.z + v2.z + v3.z;
        acc.w += v0.w + v1.w + v2.w + v3.w;
    }
    for (; j < deg; ++j) {
        float4 v = ((const float4*)(feat + (size_t)es[j] * FEATS))[lane];
        acc.x += v.x; acc.y += v.y; acc.z += v.z; acc.w += v.w;
    }
    float inv = 1.0f / (float)max(deg, 1);
    acc.x *= inv; acc.y *= inv; acc.z *= inv; acc.w *= inv;
    ((float4*)(g_accum + (size_t)node * FEATS))[lane] = acc;
}

// ---------------------------------------------------------------------------
// Weight transpose
// ---------------------------------------------------------------------------
__global__ void k_transpose(const float* __restrict__ Wn, const float* __restrict__ Ws) {
    int i = blockIdx.x * blockDim.x + threadIdx.x;
    if (i < FEATS * FEATS) {
        int o = i >> 7, k = i & 127;
        g_WnT[k * FEATS + o] = Wn[i];
        g_WsT[k * FEATS + o] = Ws[i];
    }
}

// ---------------------------------------------------------------------------
// Fused dual GEMM as one K=256 GEMM:  out = [feat | mean] @ [WsT; WnT] + b
// BM=128, BN=128, BK=16, 256 threads, 8x8 per thread, f32x2 packed FMA,
// double-buffered smem, one sync per k-tile.
// ---------------------------------------------------------------------------
__global__ __launch_bounds__(256) void k_gemm_fused(const float* __restrict__ feat,
                                                    const float* __restrict__ b_self,
                                                    float* __restrict__ out) {
    __shared__ float As[2][16][128];
    __shared__ float Bs[2][16][128];

    int tid = threadIdx.x;
    int m0 = blockIdx.x * 128;
    int tx = tid & 15;   // 16 col groups of 8
    int ty = tid >> 4;   // 16 row groups of 8

    unsigned long long acc2[8][4];
#pragma unroll
    for (int i = 0; i < 8; i++)
#pragma unroll
        for (int j = 0; j < 4; j++) acc2[i][j] = 0ull;

    // load-index precompute (each thread: 2 float4 from A-tile, 2 from B-tile)
    int fa0 = tid * 2, fa1 = tid * 2 + 1;
    int ar0 = fa0 >> 2, ac0 = (fa0 & 3) * 4;
    int ar1 = fa1 >> 2, ac1 = (fa1 & 3) * 4;
    int bk0 = fa0 >> 5, bo0 = (fa0 & 31) * 4;
    int bk1 = fa1 >> 5, bo1 = (fa1 & 31) * 4;
    bool m_ok0 = (m0 + ar0) < N_NODES;
    bool m_ok1 = (m0 + ar1) < N_NODES;

    float4 ra0, ra1, rb0, rb1;
    const float4 z4 = make_float4(0.f, 0.f, 0.f, 0.f);

#define GLOAD(kt)                                                                  \
    {                                                                              \
        int pass = (kt) >> 3;                                                      \
        int k0 = ((kt) & 7) * 16;                                                  \
        const float* A = pass ? g_accum : feat;                                    \
        const float* B = pass ? g_WnT : g_WsT;                                     \
        ra0 = m_ok0 ? *(const float4*)(A + (size_t)(m0 + ar0) * FEATS + k0 + ac0) : z4; \
        ra1 = m_ok1 ? *(const float4*)(A + (size_t)(m0 + ar1) * FEATS + k0 + ac1) : z4; \
        rb0 = *(const float4*)(B + (size_t)(k0 + bk0) * FEATS + bo0);              \
        rb1 = *(const float4*)(B + (size_t)(k0 + bk1) * FEATS + bo1);              \
    }

#define SSTORE(buf)                                                                \
    {                                                                              \
        As[buf][ac0 + 0][ar0] = ra0.x; As[buf][ac0 + 1][ar0] = ra0.y;              \
        As[buf][ac0 + 2][ar0] = ra0.z; As[buf][ac0 + 3][ar0] = ra0.w;              \
        As[buf][ac1 + 0][ar1] = ra1.x; As[buf][ac1 + 1][ar1] = ra1.y;              \
        As[buf][ac1 + 2][ar1] = ra1.z; As[buf][ac1 + 3][ar1] = ra1.w;              \
        *(float4*)&Bs[buf][bk0][bo0] = rb0;                                        \
        *(float4*)&Bs[buf][bk1][bo1] = rb1;                                        \
    }

    GLOAD(0);
    SSTORE(0);
    __syncthreads();

    for (int kt = 0; kt < 16; ++kt) {
        int cur = kt & 1;
        if (kt < 15) GLOAD(kt + 1);
        // compute on buffer cur
#pragma unroll
        for (int k = 0; k < 16; ++k) {
            float4 a0 = *(const float4*)&As[cur][k][ty * 8];
            float4 a1 = *(const float4*)&As[cur][k][ty * 8 + 4];
            const unsigned long long* B64 =
                (const unsigned long long*)&Bs[cur][k][tx * 8];
            unsigned long long b0 = B64[0], b1 = B64[1], b2 = B64[2], b3 = B64[3];
            unsigned long long ad[8] = {dup2(a0.x), dup2(a0.y), dup2(a0.z), dup2(a0.w),
                                        dup2(a1.x), dup2(a1.y), dup2(a1.z), dup2(a1.w)};
#pragma unroll
            for (int i = 0; i < 8; ++i) {
                ffma2(acc2[i][0], ad[i], b0);
                ffma2(acc2[i][1], ad[i], b1);
                ffma2(acc2[i][2], ad[i], b2);
                ffma2(acc2[i][3], ad[i], b3);
            }
        }
        if (kt < 15) SSTORE(1 - cur);
        __syncthreads();
    }

    // epilogue: bias + store
    float4 bia0 = *(const float4*)(b_self + tx * 8);
    float4 bia1 = *(const float4*)(b_self + tx * 8 + 4);
#pragma unroll
    for (int i = 0; i < 8; ++i) {
        int m = m0 + ty * 8 + i;
        if (m < N_NODES) {
            float2 p0 = unpack2(acc2[i][0]);
            float2 p1 = unpack2(acc2[i][1]);
            float2 p2 = unpack2(acc2[i][2]);
            float2 p3 = unpack2(acc2[i][3]);
            float4 r0 = make_float4(p0.x + bia0.x, p0.y + bia0.y,
                                    p1.x + bia0.z, p1.y + bia0.w);
            float4 r1 = make_float4(p2.x + bia1.x, p2.y + bia1.y,
                                    p3.x + bia1.z, p3.y + bia1.w);
            *(float4*)(out + (size_t)m * FEATS + tx * 8) = r0;
            *(float4*)(out + (size_t)m * FEATS + tx * 8 + 4) = r1;
        }
    }
#undef GLOAD
#undef SSTORE
}

// ---------------------------------------------------------------------------
extern "C" void kernel_launch(void* const* d_in, const int* in_sizes, int n_in,
                              void* d_out, int out_size) {
    const float* feat = (const float*)d_in[0];
    const void*  src  = d_in[1];
    const void*  dst  = d_in[2];
    const float* Wn   = (const float*)d_in[3];
    const float* Ws   = (const float*)d_in[4];
    const float* b    = (const float*)d_in[5];
    float*       out  = (float*)d_out;

    k_detect<<<1, 32>>>((const int*)src);
    k_zero_cnt<<<(N_NODES + 255) / 256, 256>>>();
    k_transpose<<<(FEATS * FEATS + 255) / 256, 256>>>(Wn, Ws);
    k_count<<<(N_EDGES + 255) / 256, 256>>>(dst);
    k_scan1<<<NB1, 512>>>();
    k_scan2<<<1, 256>>>();
    k_scan3<<<(N_NODES + 255) / 256, 256>>>();
    k_reorder<<<(N_EDGES + 255) / 256, 256>>>(src, dst);
    k_gather<<<(N_NODES * 32 + 255) / 256, 256>>>(feat);
    k_gemm_fused<<<(N_NODES + 127) / 128, 256>>>(feat, b, out);
}

// round 4
// speedup vs baseline: 1.9188x; 1.9138x over previous
#include <cuda_runtime.h>
#include <cstdint>

#define N_NODES 100000
#define N_EDGES 800000
#define FEATS 128
#define NB1 196  // ceil(100000/512)

// Scratch (allocation-free rule: device globals)
__device__ __align__(16) float g_accum[(size_t)N_NODES * FEATS];  // mean rows
__device__ __align__(16) unsigned g_Bf[32 * 16 * 32 * 2];  // tf32 fragment-ordered B [256x128]
__device__ int g_cnt[N_NODES];
__device__ int g_row[N_NODES];
__device__ int g_cursor[N_NODES];
__device__ int g_esrc[N_EDGES];
__device__ int g_btot[NB1];
__device__ int g_boff[NB1];
__device__ int g_is64;

__device__ __forceinline__ unsigned to_tf32(float f) {
    unsigned r;
    asm("cvt.rna.tf32.f32 %0, %1;" : "=r"(r) : "f"(f));
    return r;
}

// ---------------------------------------------------------------------------
// Kernel 0: detect index width (int64 vals < 2^31 => odd 32-bit words all 0)
// ---------------------------------------------------------------------------
__global__ void k_detect(const int* __restrict__ src_raw) {
    if (threadIdx.x == 0) {
        int is64 = 1;
        for (int i = 0; i < 256; ++i)
            if (src_raw[2 * i + 1] != 0) { is64 = 0; break; }
        g_is64 = is64;
    }
}

__device__ __forceinline__ int load_idx(const void* p, int e) {
    return g_is64 ? (int)((const long long*)p)[e] : ((const int*)p)[e];
}

// ---------------------------------------------------------------------------
// CSR build (unchanged from round 3)
// ---------------------------------------------------------------------------
__global__ void k_zero_cnt() {
    int i = blockIdx.x * blockDim.x + threadIdx.x;
    if (i < N_NODES) g_cnt[i] = 0;
}

__global__ __launch_bounds__(256) void k_count(const void* __restrict__ dst_p) {
    int e = blockIdx.x * blockDim.x + threadIdx.x;
    if (e >= N_EDGES) return;
    int d = load_idx(dst_p, e);
    if ((unsigned)d < N_NODES) atomicAdd(&g_cnt[d], 1);
}

__global__ __launch_bounds__(512) void k_scan1() {
    __shared__ int wsum[16];
    int i = blockIdx.x * 512 + threadIdx.x;
    int lane = threadIdx.x & 31, w = threadIdx.x >> 5;
    int v = (i < N_NODES) ? g_cnt[i] : 0;
    int incl = v;
#pragma unroll
    for (int o = 1; o < 32; o <<= 1) {
        int t = __shfl_up_sync(0xffffffffu, incl, o);
        if (lane >= o) incl += t;
    }
    if (lane == 31) wsum[w] = incl;
    __syncthreads();
    if (threadIdx.x < 16) {
        int x = wsum[threadIdx.x];
        int incl2 = x;
#pragma unroll
        for (int o = 1; o < 16; o <<= 1) {
            int t = __shfl_up_sync(0x0000ffffu, incl2, o);
            if ((int)threadIdx.x >= o) incl2 += t;
        }
        wsum[threadIdx.x] = incl2 - x;
        if (threadIdx.x == 15) g_btot[blockIdx.x] = incl2;
    }
    __syncthreads();
    if (i < N_NODES) g_row[i] = (incl - v) + wsum[w];
}

__global__ __launch_bounds__(256) void k_scan2() {
    __shared__ int wsum[8];
    int i = threadIdx.x;
    int lane = i & 31, w = i >> 5;
    int v = (i < NB1) ? g_btot[i] : 0;
    int incl = v;
#pragma unroll
    for (int o = 1; o < 32; o <<= 1) {
        int t = __shfl_up_sync(0xffffffffu, incl, o);
        if (lane >= o) incl += t;
    }
    if (lane == 31) wsum[w] = incl;
    __syncthreads();
    if (i < 8) {
        int x = wsum[i];
        int incl2 = x;
#pragma unroll
        for (int o = 1; o < 8; o <<= 1) {
            int t = __shfl_up_sync(0x000000ffu, incl2, o);
            if (i >= o) incl2 += t;
        }
        wsum[i] = incl2 - x;
    }
    __syncthreads();
    if (i < NB1) g_boff[i] = (incl - v) + wsum[w];
}

__global__ void k_scan3() {
    int i = blockIdx.x * blockDim.x + threadIdx.x;
    if (i < N_NODES) {
        int r = g_row[i] + g_boff[i >> 9];
        g_row[i] = r;
        g_cursor[i] = r;
    }
}

__global__ __launch_bounds__(256) void k_reorder(const void* __restrict__ src_p,
                                                 const void* __restrict__ dst_p) {
    int e = blockIdx.x * blockDim.x + threadIdx.x;
    if (e >= N_EDGES) return;
    int s = load_idx(src_p, e);
    int d = load_idx(dst_p, e);
    if ((unsigned)d >= N_NODES || (unsigned)s >= N_NODES) return;
    int pos = atomicAdd(&g_cursor[d], 1);
    g_esrc[pos] = s;
}

// ---------------------------------------------------------------------------
// Gather: one warp per dst node; accumulate feat rows in registers, write mean.
// ---------------------------------------------------------------------------
__global__ __launch_bounds__(256) void k_gather(const float* __restrict__ feat) {
    int node = (blockIdx.x * blockDim.x + threadIdx.x) >> 5;
    int lane = threadIdx.x & 31;
    if (node >= N_NODES) return;
    int start = g_row[node];
    int deg = g_cnt[node];
    const int* es = g_esrc + start;

    float4 acc = make_float4(0.f, 0.f, 0.f, 0.f);
    int j = 0;
    for (; j + 4 <= deg; j += 4) {
        int s0 = es[j], s1 = es[j + 1], s2 = es[j + 2], s3 = es[j + 3];
        float4 v0 = ((const float4*)(feat + (size_t)s0 * FEATS))[lane];
        float4 v1 = ((const float4*)(feat + (size_t)s1 * FEATS))[lane];
        float4 v2 = ((const float4*)(feat + (size_t)s2 * FEATS))[lane];
        float4 v3 = ((const float4*)(feat + (size_t)s3 * FEATS))[lane];
        acc.x += v0.x + v1.x + v2.x + v3.x;
        acc.y += v0.y + v1.y + v2.y + v3.y;
        acc.z += v0.z + v1.z + v2.z + v3.z;
        acc.w += v0.w + v1.w + v2.w + v3.w;
    }
    for (; j < deg; ++j) {
        float4 v = ((const float4*)(feat + (size_t)es[j] * FEATS))[lane];
        acc.x += v.x; acc.y += v.y; acc.z += v.z; acc.w += v.w;
    }
    float inv = 1.0f / (float)max(deg, 1);
    acc.x *= inv; acc.y *= inv; acc.z *= inv; acc.w *= inv;
    ((float4*)(g_accum + (size_t)node * FEATS))[lane] = acc;
}

// ---------------------------------------------------------------------------
// Build fragment-ordered tf32 B: B[k][n] = (k<128 ? Ws[n][k] : Wn[n][k-128])
// Layout: for kc in [0,32), nt in [0,16), lane in [0,32):
//   slot = (kc*16+nt)*32 + lane;  pair = { B[kc*8+lane%4][nt*8+lane/4],
//                                          B[kc*8+lane%4+4][nt*8+lane/4] }
// ---------------------------------------------------------------------------
__global__ void k_buildB(const float* __restrict__ Wn, const float* __restrict__ Ws) {
    int t = blockIdx.x * blockDim.x + threadIdx.x;
    if (t >= 32 * 16 * 32) return;
    int lane = t & 31;
    int nt = (t >> 5) & 15;
    int kc = t >> 9;
    int n = nt * 8 + (lane >> 2);
    int k0 = kc * 8 + (lane & 3);
    int k1 = k0 + 4;
    float v0 = (k0 < 128) ? Ws[n * 128 + k0] : Wn[n * 128 + (k0 - 128)];
    float v1 = (k1 < 128) ? Ws[n * 128 + k1] : Wn[n * 128 + (k1 - 128)];
    g_Bf[t * 2 + 0] = to_tf32(v0);
    g_Bf[t * 2 + 1] = to_tf32(v1);
}

// ---------------------------------------------------------------------------
// Tensor-core GEMM: out = [feat | mean] @ B + bias, tf32 mma.m16n8k8.
// BM=128, BN=128, BK=32, 256 threads (8 warps: wm=wid&1 over M64, wn=wid>>1 over N32)
// smem: Bf (full 256x128 tf32, 128KB, loaded once) + A double buffer (transposed,
// stride 132, conflict-free fragment loads).
// ---------------------------------------------------------------------------
#define A_STRIDE 132
#define A_BUF (32 * A_STRIDE)
#define BF_WORDS (32 * 16 * 32 * 2)
#define GEMM_SMEM ((BF_WORDS + 2 * A_BUF) * 4)

__global__ __launch_bounds__(256, 1) void k_gemm_tc(const float* __restrict__ feat,
                                                    const float* __restrict__ b_self,
                                                    float* __restrict__ out) {
    extern __shared__ unsigned smem_u[];
    unsigned* Bf = smem_u;
    unsigned* As = smem_u + BF_WORDS;

    int tid = threadIdx.x;
    int lane = tid & 31, wid = tid >> 5;
    int wm = wid & 1, wn = wid >> 1;
    int m0 = blockIdx.x * 128;

    // load full B fragments into smem (uint4 copy)
    {
        const uint4* src = (const uint4*)g_Bf;
        uint4* dst = (uint4*)Bf;
#pragma unroll
        for (int i = 0; i < BF_WORDS / 4 / 256; ++i)
            dst[tid + i * 256] = src[tid + i * 256];
    }

    float c[4][4][4];  // [mt][nt][reg]
#pragma unroll
    for (int a = 0; a < 4; a++)
#pragma unroll
        for (int b = 0; b < 4; b++)
#pragma unroll
            for (int r = 0; r < 4; r++) c[a][b][r] = 0.f;

    // A-tile global load mapping: each thread 4x float4
    int mloc = tid >> 3;          // 0..31 (+32*r)
    int kq = (tid & 7) * 4;       // 0,4,...,28
    float4 ra[4];
    const float4 z4 = make_float4(0.f, 0.f, 0.f, 0.f);

#define AGLOAD(kt)                                                              \
    {                                                                           \
        const float* A = ((kt) < 4) ? feat : g_accum;                           \
        int k0g = ((kt) & 3) * 32;                                              \
        _Pragma("unroll") for (int r = 0; r < 4; ++r) {                         \
            int m = m0 + mloc + 32 * r;                                         \
            ra[r] = (m < N_NODES)                                               \
                        ? *(const float4*)(A + (size_t)m * FEATS + k0g + kq)    \
                        : z4;                                                   \
        }                                                                       \
    }

#define ASTORE(buf)                                                             \
    {                                                                           \
        unsigned* Ab = As + (buf)*A_BUF;                                        \
        _Pragma("unroll") for (int r = 0; r < 4; ++r) {                         \
            int m = mloc + 32 * r;                                              \
            Ab[(kq + 0) * A_STRIDE + m] = to_tf32(ra[r].x);                     \
            Ab[(kq + 1) * A_STRIDE + m] = to_tf32(ra[r].y);                     \
            Ab[(kq + 2) * A_STRIDE + m] = to_tf32(ra[r].z);                     \
            Ab[(kq + 3) * A_STRIDE + m] = to_tf32(ra[r].w);                     \
        }                                                                       \
    }

    AGLOAD(0);
    ASTORE(0);
    __syncthreads();

    int r4 = lane >> 2, k4 = lane & 3;

    for (int kt = 0; kt < 8; ++kt) {
        int cur = kt & 1;
        if (kt < 7) AGLOAD(kt + 1);
        const unsigned* Ab = As + cur * A_BUF;
#pragma unroll
        for (int kk = 0; kk < 4; ++kk) {
            int k0 = kk * 8;
            int kc = kt * 4 + kk;
            // b fragments: 4 n-tiles, conflict-free LDS.64
            unsigned bf[4][2];
#pragma unroll
            for (int nt = 0; nt < 4; ++nt) {
                const unsigned* p = Bf + ((kc * 16 + (wn * 4 + nt)) * 32 + lane) * 2;
                uint2 v = *(const uint2*)p;
                bf[nt][0] = v.x;
                bf[nt][1] = v.y;
            }
#pragma unroll
            for (int mt = 0; mt < 4; ++mt) {
                int mb = wm * 64 + mt * 16;
                unsigned a0 = Ab[(k0 + k4) * A_STRIDE + mb + r4];
                unsigned a1 = Ab[(k0 + k4) * A_STRIDE + mb + r4 + 8];
                unsigned a2 = Ab[(k0 + k4 + 4) * A_STRIDE + mb + r4];
                unsigned a3 = Ab[(k0 + k4 + 4) * A_STRIDE + mb + r4 + 8];
#pragma unroll
                for (int nt = 0; nt < 4; ++nt) {
                    asm("mma.sync.aligned.m16n8k8.row.col.f32.tf32.tf32.f32 "
                        "{%0,%1,%2,%3}, {%4,%5,%6,%7}, {%8,%9}, {%0,%1,%2,%3};"
                        : "+f"(c[mt][nt][0]), "+f"(c[mt][nt][1]),
                          "+f"(c[mt][nt][2]), "+f"(c[mt][nt][3])
                        : "r"(a0), "r"(a1), "r"(a2), "r"(a3),
                          "r"(bf[nt][0]), "r"(bf[nt][1]));
                }
            }
        }
        __syncthreads();
        if (kt < 7) {
            ASTORE(1 - cur);
            __syncthreads();
        }
    }

    // epilogue: bias + store (c mapping: rows lane/4 +{0,8}, cols 2*(lane%4)+{0,1})
#pragma unroll
    for (int nt = 0; nt < 4; ++nt) {
        int col = wn * 32 + nt * 8 + (lane & 3) * 2;
        float b0 = b_self[col], b1 = b_self[col + 1];
#pragma unroll
        for (int mt = 0; mt < 4; ++mt) {
            int row = m0 + wm * 64 + mt * 16 + (lane >> 2);
            if (row < N_NODES) {
                float2 v0 = make_float2(c[mt][nt][0] + b0, c[mt][nt][1] + b1);
                *(float2*)(out + (size_t)row * FEATS + col) = v0;
            }
            if (row + 8 < N_NODES) {
                float2 v1 = make_float2(c[mt][nt][2] + b0, c[mt][nt][3] + b1);
                *(float2*)(out + (size_t)(row + 8) * FEATS + col) = v1;
            }
        }
    }
#undef AGLOAD
#undef ASTORE
}

// ---------------------------------------------------------------------------
extern "C" void kernel_launch(void* const* d_in, const int* in_sizes, int n_in,
                              void* d_out, int out_size) {
    const float* feat = (const float*)d_in[0];
    const void*  src  = d_in[1];
    const void*  dst  = d_in[2];
    const float* Wn   = (const float*)d_in[3];
    const float* Ws   = (const float*)d_in[4];
    const float* b    = (const float*)d_in[5];
    float*       out  = (float*)d_out;

    cudaFuncSetAttribute(k_gemm_tc, cudaFuncAttributeMaxDynamicSharedMemorySize,
                         GEMM_SMEM);

    k_detect<<<1, 32>>>((const int*)src);
    k_zero_cnt<<<(N_NODES + 255) / 256, 256>>>();
    k_buildB<<<(32 * 16 * 32 + 255) / 256, 256>>>(Wn, Ws);
    k_count<<<(N_EDGES + 255) / 256, 256>>>(dst);
    k_scan1<<<NB1, 512>>>();
    k_scan2<<<1, 256>>>();
    k_scan3<<<(N_NODES + 255) / 256, 256>>>();
    k_reorder<<<(N_EDGES + 255) / 256, 256>>>(src, dst);
    k_gather<<<(N_NODES * 32 + 255) / 256, 256>>>(feat);
    k_gemm_tc<<<(N_NODES + 127) / 128, 256, GEMM_SMEM>>>(feat, b, out);
}